// round 3
// baseline (speedup 1.0000x reference)
#include <cuda_runtime.h>
#include <cstdint>

// ---------------------------------------------------------------------------
// out[b,i,j] = sum_d relu(a[b,i,d] + c[b,j,d]) * W2[d] + b2
//   a = emb @ W1[:768] + b1,  c = emb @ W1[768:]
// emb (4,512,768) f32, W1 (1536,256), b1 (256), W2 (256,1), b2 (1)
// out (4,512,512) f32
// ---------------------------------------------------------------------------

#define B_   4
#define N_   512
#define H_   768
#define HID_ 256
#define M_   (B_ * N_)        // 2048

// Scratch, D-MAJOR: g_a[d * M_ + m]  (m = b*512 + i)
__device__ float g_a[HID_ * M_];
__device__ float g_c[HID_ * M_];

__device__ __forceinline__ float2 ffma2(float2 a, float2 b, float2 c) {
    union F2U { float2 f; unsigned long long u; };
    F2U A, Bv, C, D;
    A.f = a; Bv.f = b; C.f = c;
    asm("fma.rn.f32x2 %0, %1, %2, %3;"
        : "=l"(D.u) : "l"(A.u), "l"(Bv.u), "l"(C.u));
    return D.f;
}
__device__ __forceinline__ float2 fadd2(float2 a, float2 b) {
    union F2U { float2 f; unsigned long long u; };
    F2U A, Bv, D;
    A.f = a; Bv.f = b;
    asm("add.rn.f32x2 %0, %1, %2;"
        : "=l"(D.u) : "l"(A.u), "l"(Bv.u));
    return D.f;
}

// ---------------------------------------------------------------------------
// Kernel 1: GEMM, one half per grid.z. Tile 64m x 32n, BK=32, 128 threads,
// 4m x 4n per thread. Double-buffered smem + register prefetch: one sync/iter.
// Epilogue stores TRANSPOSED (d-major) to g_a / g_c.  Grid 8x32x2 = 512.
// ---------------------------------------------------------------------------
#define GBK   32
#define GKIT  (H_ / GBK)   // 24

__global__ void __launch_bounds__(128)
gemm_kernel(const float* __restrict__ emb, const float* __restrict__ W1,
            const float* __restrict__ b1)
{
    const int half = blockIdx.z;
    const float* __restrict__ W = W1 + half * (H_ * HID_);
    float* __restrict__ gout = half ? g_c : g_a;

    const int m0 = blockIdx.y * 64;
    const int n0 = blockIdx.x * 32;

    __shared__ float As[2][GBK][68];   // [k][m], 64m + pad
    __shared__ float Bs[2][GBK][36];   // [k][n], 32n + pad

    const int t  = threadIdx.x;        // 128
    const int tx = t & 7;              // 4 n each -> 32n
    const int ty = t >> 3;             // 4 m each -> 64m

    // fill indices
    const int ar = t & 63;             // emb row
    const int aq = (t >> 6) * 16;      // emb k base (covers aq..aq+15)
    const int bk = t >> 3;             // W k row (and +16)
    const int bn = (t & 7) * 4;

    float4 pa[4], pb0, pb1;

    // prefetch tile 0
    #pragma unroll
    for (int e = 0; e < 4; e++)
        pa[e] = *(const float4*)&emb[(m0 + ar) * H_ + aq + 4 * e];
    pb0 = *(const float4*)&W[(bk)      * HID_ + n0 + bn];
    pb1 = *(const float4*)&W[(bk + 16) * HID_ + n0 + bn];

    // store tile 0
    #pragma unroll
    for (int e = 0; e < 4; e++) {
        As[0][aq + 4*e + 0][ar] = pa[e].x; As[0][aq + 4*e + 1][ar] = pa[e].y;
        As[0][aq + 4*e + 2][ar] = pa[e].z; As[0][aq + 4*e + 3][ar] = pa[e].w;
    }
    *(float4*)&Bs[0][bk][bn]      = pb0;
    *(float4*)&Bs[0][bk + 16][bn] = pb1;
    __syncthreads();

    float2 acc[4][2];
    #pragma unroll
    for (int mi = 0; mi < 4; mi++) {
        acc[mi][0] = make_float2(0.f, 0.f);
        acc[mi][1] = make_float2(0.f, 0.f);
    }

    for (int it = 0; it < GKIT; it++) {
        const int cur = it & 1;
        if (it + 1 < GKIT) {
            const int k0 = (it + 1) * GBK;
            #pragma unroll
            for (int e = 0; e < 4; e++)
                pa[e] = *(const float4*)&emb[(m0 + ar) * H_ + k0 + aq + 4 * e];
            pb0 = *(const float4*)&W[(k0 + bk)      * HID_ + n0 + bn];
            pb1 = *(const float4*)&W[(k0 + bk + 16) * HID_ + n0 + bn];
        }

        #pragma unroll
        for (int k = 0; k < GBK; k++) {
            const float4 av = *(const float4*)&As[cur][k][ty * 4];
            const float4 bv = *(const float4*)&Bs[cur][k][tx * 4];
            const float2 b01 = make_float2(bv.x, bv.y);
            const float2 b23 = make_float2(bv.z, bv.w);
            const float am[4] = {av.x, av.y, av.z, av.w};
            #pragma unroll
            for (int mi = 0; mi < 4; mi++) {
                const float2 ap = make_float2(am[mi], am[mi]);
                acc[mi][0] = ffma2(ap, b01, acc[mi][0]);
                acc[mi][1] = ffma2(ap, b23, acc[mi][1]);
            }
        }

        if (it + 1 < GKIT) {
            const int nb = 1 - cur;
            #pragma unroll
            for (int e = 0; e < 4; e++) {
                As[nb][aq + 4*e + 0][ar] = pa[e].x; As[nb][aq + 4*e + 1][ar] = pa[e].y;
                As[nb][aq + 4*e + 2][ar] = pa[e].z; As[nb][aq + 4*e + 3][ar] = pa[e].w;
            }
            *(float4*)&Bs[nb][bk][bn]      = pb0;
            *(float4*)&Bs[nb][bk + 16][bn] = pb1;
            __syncthreads();
        }
    }

    // Epilogue: transposed (d-major) store, float4 over m; +b1 on a-half
    float4 b1v = make_float4(0.f, 0.f, 0.f, 0.f);
    if (half == 0) b1v = *(const float4*)&b1[n0 + tx * 4];
    const float bias[4] = {b1v.x, b1v.y, b1v.z, b1v.w};
    const int mm = m0 + ty * 4;
    #pragma unroll
    for (int jj = 0; jj < 4; jj++) {
        const int p = jj >> 1;
        const int n = n0 + tx * 4 + jj;
        float4 o;
        if (jj & 1) {
            o.x = acc[0][p].y + bias[jj]; o.y = acc[1][p].y + bias[jj];
            o.z = acc[2][p].y + bias[jj]; o.w = acc[3][p].y + bias[jj];
        } else {
            o.x = acc[0][p].x + bias[jj]; o.y = acc[1][p].x + bias[jj];
            o.z = acc[2][p].x + bias[jj]; o.w = acc[3][p].x + bias[jj];
        }
        *(float4*)&gout[n * M_ + mm] = o;
    }
}

// ---------------------------------------------------------------------------
// Kernel 2: pairwise relu-dot. Tile 32i x 32j, 64 threads, 4i x 4j/thread.
// Grid 16x16x4 = 1024... -> (512/32)^2 * 4 = 1024? no: 16*16*4 = 1024 blocks.
// d-major scratch -> coalesced float4 fills. Double-buffered + prefetch.
// Per dk/thread: 2 LDS + 8 ADD2 + 16 FMNMX + 8 FFMA2 (2 B LDS per output*d).
// ---------------------------------------------------------------------------
#define PDK  32
#define PDIT (HID_ / PDK)   // 8

__global__ void __launch_bounds__(64)
pair_kernel(const float* __restrict__ W2, const float* __restrict__ b2,
            float* __restrict__ out)
{
    const int b  = blockIdx.z;
    const int i0 = blockIdx.y * 32;
    const int j0 = blockIdx.x * 32;
    const int ma = b * N_ + i0;
    const int mc = b * N_ + j0;

    __shared__ float As[2][PDK][36];
    __shared__ float Cs[2][PDK][36];
    __shared__ float Ws[HID_];

    const int t  = threadIdx.x;     // 64
    const int tx = t & 7;           // 4 j each
    const int ty = t >> 3;          // 4 i each

    Ws[t] = W2[t]; Ws[t + 64] = W2[t + 64];
    Ws[t + 128] = W2[t + 128]; Ws[t + 192] = W2[t + 192];

    const int fdk = t >> 1;         // 0..31
    const int fs  = (t & 1) * 16;   // 0 or 16

    float4 paf[4], pcf[4];

    // prefetch + store tile 0
    {
        const float* __restrict__ pa = &g_a[fdk * M_ + ma + fs];
        const float* __restrict__ pc = &g_c[fdk * M_ + mc + fs];
        #pragma unroll
        for (int e = 0; e < 4; e++) { paf[e] = *(const float4*)(pa + 4*e);
                                      pcf[e] = *(const float4*)(pc + 4*e); }
        #pragma unroll
        for (int e = 0; e < 4; e++) {
            *(float4*)&As[0][fdk][fs + 4*e] = paf[e];
            *(float4*)&Cs[0][fdk][fs + 4*e] = pcf[e];
        }
    }
    __syncthreads();

    float2 acc[4][2];
    #pragma unroll
    for (int mi = 0; mi < 4; mi++) {
        acc[mi][0] = make_float2(0.f, 0.f);
        acc[mi][1] = make_float2(0.f, 0.f);
    }

    for (int it = 0; it < PDIT; it++) {
        const int cur = it & 1;
        if (it + 1 < PDIT) {
            const int d0 = (it + 1) * PDK;
            const float* __restrict__ pa = &g_a[(d0 + fdk) * M_ + ma + fs];
            const float* __restrict__ pc = &g_c[(d0 + fdk) * M_ + mc + fs];
            #pragma unroll
            for (int e = 0; e < 4; e++) { paf[e] = *(const float4*)(pa + 4*e);
                                          pcf[e] = *(const float4*)(pc + 4*e); }
        }

        const int dbase = it * PDK;
        #pragma unroll
        for (int g = 0; g < PDK / 4; g++) {
            const float4 wv = *(const float4*)&Ws[dbase + g * 4];
            const float wr[4] = {wv.x, wv.y, wv.z, wv.w};
            #pragma unroll
            for (int e = 0; e < 4; e++) {
                const int dk = g * 4 + e;
                const float2 wp = make_float2(wr[e], wr[e]);
                const float4 av = *(const float4*)&As[cur][dk][ty * 4];
                const float4 cv = *(const float4*)&Cs[cur][dk][tx * 4];
                const float2 c01 = make_float2(cv.x, cv.y);
                const float2 c23 = make_float2(cv.z, cv.w);
                const float am[4] = {av.x, av.y, av.z, av.w};
                #pragma unroll
                for (int mi = 0; mi < 4; mi++) {
                    const float2 ap = make_float2(am[mi], am[mi]);
                    float2 s0 = fadd2(ap, c01);
                    float2 s1 = fadd2(ap, c23);
                    s0.x = fmaxf(s0.x, 0.f); s0.y = fmaxf(s0.y, 0.f);
                    s1.x = fmaxf(s1.x, 0.f); s1.y = fmaxf(s1.y, 0.f);
                    acc[mi][0] = ffma2(s0, wp, acc[mi][0]);
                    acc[mi][1] = ffma2(s1, wp, acc[mi][1]);
                }
            }
        }

        if (it + 1 < PDIT) {
            const int nb = 1 - cur;
            #pragma unroll
            for (int e = 0; e < 4; e++) {
                *(float4*)&As[nb][fdk][fs + 4*e] = paf[e];
                *(float4*)&Cs[nb][fdk][fs + 4*e] = pcf[e];
            }
            __syncthreads();
        }
    }

    const float bb = b2[0];
    const int j = j0 + tx * 4;
    #pragma unroll
    for (int mi = 0; mi < 4; mi++) {
        const int i = i0 + ty * 4 + mi;
        float4 o;
        o.x = acc[mi][0].x + bb;
        o.y = acc[mi][0].y + bb;
        o.z = acc[mi][1].x + bb;
        o.w = acc[mi][1].y + bb;
        *(float4*)&out[((size_t)b * N_ + i) * N_ + j] = o;
    }
}

// ---------------------------------------------------------------------------
extern "C" void kernel_launch(void* const* d_in, const int* in_sizes, int n_in,
                              void* d_out, int out_size)
{
    const float* emb = (const float*)d_in[0];
    const float* W1  = (const float*)d_in[1];
    const float* b1  = (const float*)d_in[2];
    const float* W2  = (const float*)d_in[3];
    const float* b2  = (const float*)d_in[4];
    float* out = (float*)d_out;

    dim3 ggrid(HID_ / 32, M_ / 64, 2);       // 8 x 32 x 2 = 512 blocks
    gemm_kernel<<<ggrid, 128>>>(emb, W1, b1);

    dim3 pgrid(N_ / 32, N_ / 32, B_);        // 16 x 16 x 4 = 1024 blocks
    pair_kernel<<<pgrid, 64>>>(W2, b2, out);
}

// round 5
// speedup vs baseline: 1.3894x; 1.3894x over previous
#include <cuda_runtime.h>
#include <cuda_bf16.h>
#include <cstdint>

// ---------------------------------------------------------------------------
// out[b,i,j] = sum_d relu(a[b,i,d] + c[b,j,d]) * W2[d] + b2
//   a = emb @ W1[:768] + b1,  c = emb @ W1[768:]
// emb (4,512,768) f32, W1 (1536,256), b1 (256), W2 (256,1), b2 (1)
// out (4,512,512) f32
//
//  prep : emb -> bf16 hi/lo planes; W1 -> B[n][k] bf16 hi/lo (n = 512 rows)
//  gemm : mma.sync m16n8k16 bf16, 3-term split (hi*hi + hi*lo + lo*hi),
//         CTA 128m x 64n, 8 warps (32x32 each), BK=32, double-buffered smem
//  pair : scalar relu-dot (best measured config, unchanged)
// ---------------------------------------------------------------------------

#define B_   4
#define N_   512
#define H_   768
#define HID_ 256
#define M_   (B_ * N_)        // 2048

__device__ float g_a[HID_ * M_];                 // d-major: g_a[d*M_+m]
__device__ float g_c[HID_ * M_];
__device__ __nv_bfloat16 g_ehi[M_ * H_];         // emb planes, row-major [m][k]
__device__ __nv_bfloat16 g_elo[M_ * H_];
__device__ __nv_bfloat16 g_bhi[N_ * H_];         // B[n][k], n = half*256 + d
__device__ __nv_bfloat16 g_blo[N_ * H_];

// ---------------- helpers ---------------------------------------------------
__device__ __forceinline__ uint32_t smem_u32(const void* p) {
    uint32_t a;
    asm("{ .reg .u64 t; cvta.to.shared.u64 t, %1; cvt.u32.u64 %0, t; }"
        : "=r"(a) : "l"(p));
    return a;
}
__device__ __forceinline__ void ldmx4(uint32_t addr, uint32_t* r) {
    asm volatile("ldmatrix.sync.aligned.m8n8.x4.shared.b16 {%0,%1,%2,%3}, [%4];"
                 : "=r"(r[0]), "=r"(r[1]), "=r"(r[2]), "=r"(r[3]) : "r"(addr));
}
__device__ __forceinline__ void mma16816(float* c, const uint32_t* a,
                                         uint32_t b0, uint32_t b1) {
    asm volatile(
        "mma.sync.aligned.m16n8k16.row.col.f32.bf16.bf16.f32 "
        "{%0,%1,%2,%3}, {%4,%5,%6,%7}, {%8,%9}, {%0,%1,%2,%3};"
        : "+f"(c[0]), "+f"(c[1]), "+f"(c[2]), "+f"(c[3])
        : "r"(a[0]), "r"(a[1]), "r"(a[2]), "r"(a[3]), "r"(b0), "r"(b1));
}
// packed fp32x2 (pair kernel)
__device__ __forceinline__ float2 ffma2(float2 a, float2 b, float2 c) {
    union F2U { float2 f; unsigned long long u; };
    F2U A, Bv, C, D;
    A.f = a; Bv.f = b; C.f = c;
    asm("fma.rn.f32x2 %0, %1, %2, %3;" : "=l"(D.u) : "l"(A.u), "l"(Bv.u), "l"(C.u));
    return D.f;
}
__device__ __forceinline__ float2 fadd2(float2 a, float2 b) {
    union F2U { float2 f; unsigned long long u; };
    F2U A, Bv, D;
    A.f = a; Bv.f = b;
    asm("add.rn.f32x2 %0, %1, %2;" : "=l"(D.u) : "l"(A.u), "l"(Bv.u));
    return D.f;
}

// ---------------------------------------------------------------------------
// Prep 1: split emb (f32) into bf16 hi + lo planes. 4 elems / thread.
// ---------------------------------------------------------------------------
__global__ void __launch_bounds__(256)
emb_split_kernel(const float* __restrict__ emb)
{
    const int idx = (blockIdx.x * 256 + threadIdx.x) * 4;
    float4 v = *(const float4*)&emb[idx];
    __nv_bfloat16 h0 = __float2bfloat16(v.x), h1 = __float2bfloat16(v.y);
    __nv_bfloat16 h2 = __float2bfloat16(v.z), h3 = __float2bfloat16(v.w);
    __nv_bfloat16 l0 = __float2bfloat16(v.x - __bfloat162float(h0));
    __nv_bfloat16 l1 = __float2bfloat16(v.y - __bfloat162float(h1));
    __nv_bfloat16 l2 = __float2bfloat16(v.z - __bfloat162float(h2));
    __nv_bfloat16 l3 = __float2bfloat16(v.w - __bfloat162float(h3));
    *(__nv_bfloat162*)&g_ehi[idx]     = __nv_bfloat162(h0, h1);
    *(__nv_bfloat162*)&g_ehi[idx + 2] = __nv_bfloat162(h2, h3);
    *(__nv_bfloat162*)&g_elo[idx]     = __nv_bfloat162(l0, l1);
    *(__nv_bfloat162*)&g_elo[idx + 2] = __nv_bfloat162(l2, l3);
}

// ---------------------------------------------------------------------------
// Prep 2: W1 (1536 x 256) -> B[n][k] bf16 hi/lo, n = half*256 + d (512 rows).
// ---------------------------------------------------------------------------
__global__ void __launch_bounds__(256)
w_split_kernel(const float* __restrict__ W1)
{
    const int idx = blockIdx.x * 256 + threadIdx.x;     // 512 * 192
    const int k4 = idx % (H_ / 4);
    const int n  = idx / (H_ / 4);                       // 0..511
    const int half = n >> 8;
    const int d    = n & 255;
    const int k = k4 * 4;

    __nv_bfloat16 h[4], l[4];
    #pragma unroll
    for (int e = 0; e < 4; e++) {
        float x = W1[(half * H_ + k + e) * HID_ + d];
        h[e] = __float2bfloat16(x);
        l[e] = __float2bfloat16(x - __bfloat162float(h[e]));
    }
    const int o = n * H_ + k;
    *(__nv_bfloat162*)&g_bhi[o]     = __nv_bfloat162(h[0], h[1]);
    *(__nv_bfloat162*)&g_bhi[o + 2] = __nv_bfloat162(h[2], h[3]);
    *(__nv_bfloat162*)&g_blo[o]     = __nv_bfloat162(l[0], l[1]);
    *(__nv_bfloat162*)&g_blo[o + 2] = __nv_bfloat162(l[2], l[3]);
}

// ---------------------------------------------------------------------------
// GEMM: D[2048, 512] = sum over 3 planes of A_p (2048x768) @ B_p^T (512x768)
// CTA: 128m x 64n, 256 thr (8 warps: warp_m = wid&3 (32m), warp_n = wid>>2 (32n))
// BK=32 -> 72 k-iters. Double-buffered smem, 80B row stride (ldmatrix clean).
// Epilogue: d-major store to g_a/g_c, +b1 on half 0. Grid 8 x 16 = 128 CTAs.
// ---------------------------------------------------------------------------
#define GBK    32
#define KITERS (3 * (H_ / GBK))   // 72
#define A_ELEM (128 * 40)         // per buffer
#define B_ELEM (64 * 40)

__global__ void __launch_bounds__(256)
gemm_kernel(const float* __restrict__ b1)
{
    __shared__ __nv_bfloat16 As[2][A_ELEM];
    __shared__ __nv_bfloat16 Bs[2][B_ELEM];
    __shared__ float b1s[64];

    const int t      = threadIdx.x;
    const int lane   = t & 31;
    const int wid    = t >> 5;
    const int warp_m = wid & 3;           // 32 m each
    const int warp_n = wid >> 2;          // 32 n each
    const int m0     = blockIdx.y * 128;
    const int ng0    = blockIdx.x * 64;   // global n (0..511)
    const int half   = ng0 >> 8;
    const int d0     = ng0 & 255;

    if (t < 64) b1s[t] = (half == 0) ? b1[d0 + t] : 0.f;

    // fill indices: A slots t and t+256 (512 slots of 16B), B slot t
    const int ar0 = t >> 2,          ak0 = (t & 3) * 8;
    const int ar1 = (t + 256) >> 2,  ak1 = ((t + 256) & 3) * 8;
    const int br  = t >> 2,          bk  = (t & 3) * 8;

    const __nv_bfloat16* __restrict__ Ap[3] = {g_ehi, g_ehi, g_elo};
    const __nv_bfloat16* __restrict__ Bp[3] = {g_bhi, g_blo, g_bhi};

    uint4 pa0, pa1, pb;
    auto ldg_it = [&](int it) {
        const int p  = it / 24;
        const int k0 = (it % 24) * GBK;
        const __nv_bfloat16* __restrict__ ea = Ap[p];
        const __nv_bfloat16* __restrict__ eb = Bp[p];
        pa0 = *(const uint4*)&ea[(m0 + ar0) * H_ + k0 + ak0];
        pa1 = *(const uint4*)&ea[(m0 + ar1) * H_ + k0 + ak1];
        pb  = *(const uint4*)&eb[(ng0 + br) * H_ + k0 + bk];
    };
    auto sts_buf = [&](int nb) {
        *(uint4*)&As[nb][ar0 * 40 + ak0] = pa0;
        *(uint4*)&As[nb][ar1 * 40 + ak1] = pa1;
        *(uint4*)&Bs[nb][br * 40 + bk]   = pb;
    };

    ldg_it(0);
    sts_buf(0);
    __syncthreads();

    float acc[2][4][4];
    #pragma unroll
    for (int mf = 0; mf < 2; mf++)
        #pragma unroll
        for (int nf = 0; nf < 4; nf++)
            #pragma unroll
            for (int e = 0; e < 4; e++) acc[mf][nf][e] = 0.f;

    // ldmatrix per-lane byte offsets (row-within-16, k-half select)
    const uint32_t sA = smem_u32(As);
    const uint32_t sB = smem_u32(Bs);
    const uint32_t lane_off = (uint32_t)(((lane & 15) * 40 + (lane >> 4) * 8) * 2);
    const uint32_t aw = sA + (uint32_t)(warp_m * 32 * 80) + lane_off;
    const uint32_t bw = sB + (uint32_t)(warp_n * 32 * 80) + lane_off;

    for (int it = 0; it < KITERS; it++) {
        const int cur = it & 1;
        if (it + 1 < KITERS) ldg_it(it + 1);

        const uint32_t aB = aw + (uint32_t)cur * (A_ELEM * 2);
        const uint32_t bB = bw + (uint32_t)cur * (B_ELEM * 2);
        #pragma unroll
        for (int kk = 0; kk < 2; kk++) {
            uint32_t a0[4], a1[4], b0[4], b1r[4];
            ldmx4(aB + kk * 32,            a0);   // m0-15
            ldmx4(aB + kk * 32 + 16 * 80,  a1);   // m16-31
            ldmx4(bB + kk * 32,            b0);   // n0-15
            ldmx4(bB + kk * 32 + 16 * 80,  b1r);  // n16-31
            mma16816(acc[0][0], a0, b0[0],  b0[2]);
            mma16816(acc[0][1], a0, b0[1],  b0[3]);
            mma16816(acc[0][2], a0, b1r[0], b1r[2]);
            mma16816(acc[0][3], a0, b1r[1], b1r[3]);
            mma16816(acc[1][0], a1, b0[0],  b0[2]);
            mma16816(acc[1][1], a1, b0[1],  b0[3]);
            mma16816(acc[1][2], a1, b1r[0], b1r[2]);
            mma16816(acc[1][3], a1, b1r[1], b1r[3]);
        }

        if (it + 1 < KITERS) {
            sts_buf(1 - cur);
            __syncthreads();
        }
    }

    // Epilogue: d-major store (+b1 already zeroed for half 1)
    float* __restrict__ gout = half ? g_c : g_a;
    const int mrow = m0 + warp_m * 32 + (lane >> 2);
    #pragma unroll
    for (int mf = 0; mf < 2; mf++) {
        const int m = mrow + mf * 16;
        #pragma unroll
        for (int nf = 0; nf < 4; nf++) {
            const int nl = warp_n * 32 + nf * 8 + (lane & 3) * 2;
            const float bias0 = b1s[nl], bias1 = b1s[nl + 1];
            const int d = d0 + nl;
            gout[d       * M_ + m]     = acc[mf][nf][0] + bias0;
            gout[(d + 1) * M_ + m]     = acc[mf][nf][1] + bias1;
            gout[d       * M_ + m + 8] = acc[mf][nf][2] + bias0;
            gout[(d + 1) * M_ + m + 8] = acc[mf][nf][3] + bias1;
        }
    }
}

// ---------------------------------------------------------------------------
// Pair kernel: unchanged (32x32 tiles, 64 thr, 4x4/thread, d-major scratch,
// double-buffered smem + reg prefetch). Measured 33.2us.
// ---------------------------------------------------------------------------
#define PDK  32
#define PDIT (HID_ / PDK)   // 8

__global__ void __launch_bounds__(64)
pair_kernel(const float* __restrict__ W2, const float* __restrict__ b2,
            float* __restrict__ out)
{
    const int b  = blockIdx.z;
    const int i0 = blockIdx.y * 32;
    const int j0 = blockIdx.x * 32;
    const int ma = b * N_ + i0;
    const int mc = b * N_ + j0;

    __shared__ float As[2][PDK][36];
    __shared__ float Cs[2][PDK][36];
    __shared__ float Ws[HID_];

    const int t  = threadIdx.x;
    const int tx = t & 7;
    const int ty = t >> 3;

    Ws[t] = W2[t]; Ws[t + 64] = W2[t + 64];
    Ws[t + 128] = W2[t + 128]; Ws[t + 192] = W2[t + 192];

    const int fdk = t >> 1;
    const int fs  = (t & 1) * 16;

    float4 paf[4], pcf[4];
    {
        const float* __restrict__ pa = &g_a[fdk * M_ + ma + fs];
        const float* __restrict__ pc = &g_c[fdk * M_ + mc + fs];
        #pragma unroll
        for (int e = 0; e < 4; e++) { paf[e] = *(const float4*)(pa + 4*e);
                                      pcf[e] = *(const float4*)(pc + 4*e); }
        #pragma unroll
        for (int e = 0; e < 4; e++) {
            *(float4*)&As[0][fdk][fs + 4*e] = paf[e];
            *(float4*)&Cs[0][fdk][fs + 4*e] = pcf[e];
        }
    }
    __syncthreads();

    float2 acc[4][2];
    #pragma unroll
    for (int mi = 0; mi < 4; mi++) {
        acc[mi][0] = make_float2(0.f, 0.f);
        acc[mi][1] = make_float2(0.f, 0.f);
    }

    for (int it = 0; it < PDIT; it++) {
        const int cur = it & 1;
        if (it + 1 < PDIT) {
            const int dd = (it + 1) * PDK;
            const float* __restrict__ pa = &g_a[(dd + fdk) * M_ + ma + fs];
            const float* __restrict__ pc = &g_c[(dd + fdk) * M_ + mc + fs];
            #pragma unroll
            for (int e = 0; e < 4; e++) { paf[e] = *(const float4*)(pa + 4*e);
                                          pcf[e] = *(const float4*)(pc + 4*e); }
        }

        const int dbase = it * PDK;
        #pragma unroll
        for (int g = 0; g < PDK / 4; g++) {
            const float4 wv = *(const float4*)&Ws[dbase + g * 4];
            const float wr[4] = {wv.x, wv.y, wv.z, wv.w};
            #pragma unroll
            for (int e = 0; e < 4; e++) {
                const int dk = g * 4 + e;
                const float2 wp = make_float2(wr[e], wr[e]);
                const float4 av = *(const float4*)&As[cur][dk][ty * 4];
                const float4 cv = *(const float4*)&Cs[cur][dk][tx * 4];
                const float2 c01 = make_float2(cv.x, cv.y);
                const float2 c23 = make_float2(cv.z, cv.w);
                const float am[4] = {av.x, av.y, av.z, av.w};
                #pragma unroll
                for (int mi = 0; mi < 4; mi++) {
                    const float2 ap = make_float2(am[mi], am[mi]);
                    float2 s0 = fadd2(ap, c01);
                    float2 s1 = fadd2(ap, c23);
                    s0.x = fmaxf(s0.x, 0.f); s0.y = fmaxf(s0.y, 0.f);
                    s1.x = fmaxf(s1.x, 0.f); s1.y = fmaxf(s1.y, 0.f);
                    acc[mi][0] = ffma2(s0, wp, acc[mi][0]);
                    acc[mi][1] = ffma2(s1, wp, acc[mi][1]);
                }
            }
        }

        if (it + 1 < PDIT) {
            const int nb = 1 - cur;
            #pragma unroll
            for (int e = 0; e < 4; e++) {
                *(float4*)&As[nb][fdk][fs + 4*e] = paf[e];
                *(float4*)&Cs[nb][fdk][fs + 4*e] = pcf[e];
            }
            __syncthreads();
        }
    }

    const float bb = b2[0];
    const int j = j0 + tx * 4;
    #pragma unroll
    for (int mi = 0; mi < 4; mi++) {
        const int i = i0 + ty * 4 + mi;
        float4 o;
        o.x = acc[mi][0].x + bb;
        o.y = acc[mi][0].y + bb;
        o.z = acc[mi][1].x + bb;
        o.w = acc[mi][1].y + bb;
        *(float4*)&out[((size_t)b * N_ + i) * N_ + j] = o;
    }
}

// ---------------------------------------------------------------------------
extern "C" void kernel_launch(void* const* d_in, const int* in_sizes, int n_in,
                              void* d_out, int out_size)
{
    const float* emb = (const float*)d_in[0];
    const float* W1  = (const float*)d_in[1];
    const float* b1  = (const float*)d_in[2];
    const float* W2  = (const float*)d_in[3];
    const float* b2  = (const float*)d_in[4];
    float* out = (float*)d_out;

    emb_split_kernel<<<(M_ * H_) / (256 * 4), 256>>>(emb);   // 1536 blocks
    w_split_kernel<<<(N_ * (H_ / 4)) / 256, 256>>>(W1);      // 384 blocks

    dim3 ggrid(N_ / 64, M_ / 128);                           // 8 x 16 = 128
    gemm_kernel<<<ggrid, 256>>>(b1);

    dim3 pgrid(N_ / 32, N_ / 32, B_);                        // 16 x 16 x 4
    pair_kernel<<<pgrid, 64>>>(W2, b2, out);
}

// round 6
// speedup vs baseline: 1.7436x; 1.2549x over previous
#include <cuda_runtime.h>
#include <cuda_bf16.h>
#include <cstdint>

// ---------------------------------------------------------------------------
// out[b,i,j] = sum_d relu(a[b,i,d] + c[b,j,d]) * W2[d] + b2
//   a = emb @ W1[:768] + b1,  c = emb @ W1[768:]
// emb (4,512,768) f32, W1 (1536,256), b1 (256), W2 (256,1), b2 (1)
// out (4,512,512) f32
//
//  prep : emb -> bf16 hi/lo planes; W1 -> B[n][k] bf16 hi/lo (512 n-rows)
//  gemm : mma.sync m16n8k16 bf16, 3 planes (hi*hi + hi*lo + lo*hi),
//         CTA 128m x 64n, BK=64, cp.async double-buffer, SW128 smem
//  pair : scalar relu-dot (measured 34.4us, unchanged)
// ---------------------------------------------------------------------------

#define B_   4
#define N_   512
#define H_   768
#define HID_ 256
#define M_   (B_ * N_)        // 2048

__device__ float g_a[HID_ * M_];                 // d-major: g_a[d*M_+m]
__device__ float g_c[HID_ * M_];
__device__ __nv_bfloat16 g_ehi[M_ * H_];         // emb planes, row-major [m][k]
__device__ __nv_bfloat16 g_elo[M_ * H_];
__device__ __nv_bfloat16 g_bhi[N_ * H_];         // B[n][k], n = half*256 + d
__device__ __nv_bfloat16 g_blo[N_ * H_];

// ---------------- helpers ---------------------------------------------------
__device__ __forceinline__ uint32_t smem_u32(const void* p) {
    uint32_t a;
    asm("{ .reg .u64 t; cvta.to.shared.u64 t, %1; cvt.u32.u64 %0, t; }"
        : "=r"(a) : "l"(p));
    return a;
}
#define SW128(o) ((o) ^ (((o) >> 3) & 0x70))

__device__ __forceinline__ void cp_async16(uint32_t dst, const void* src) {
    asm volatile("cp.async.cg.shared.global [%0], [%1], 16;"
                 :: "r"(dst), "l"(src) : "memory");
}
__device__ __forceinline__ void cp_commit() {
    asm volatile("cp.async.commit_group;" ::: "memory");
}
__device__ __forceinline__ void cp_wait0() {
    asm volatile("cp.async.wait_group 0;" ::: "memory");
}
__device__ __forceinline__ void ldmx4(uint32_t addr, uint32_t* r) {
    asm volatile("ldmatrix.sync.aligned.m8n8.x4.shared.b16 {%0,%1,%2,%3}, [%4];"
                 : "=r"(r[0]), "=r"(r[1]), "=r"(r[2]), "=r"(r[3]) : "r"(addr));
}
__device__ __forceinline__ void mma16816(float* c, const uint32_t* a,
                                         uint32_t b0, uint32_t b1) {
    asm volatile(
        "mma.sync.aligned.m16n8k16.row.col.f32.bf16.bf16.f32 "
        "{%0,%1,%2,%3}, {%4,%5,%6,%7}, {%8,%9}, {%0,%1,%2,%3};"
        : "+f"(c[0]), "+f"(c[1]), "+f"(c[2]), "+f"(c[3])
        : "r"(a[0]), "r"(a[1]), "r"(a[2]), "r"(a[3]), "r"(b0), "r"(b1));
}
// packed fp32x2 (pair kernel)
__device__ __forceinline__ float2 ffma2(float2 a, float2 b, float2 c) {
    union F2U { float2 f; unsigned long long u; };
    F2U A, Bv, C, D;
    A.f = a; Bv.f = b; C.f = c;
    asm("fma.rn.f32x2 %0, %1, %2, %3;" : "=l"(D.u) : "l"(A.u), "l"(Bv.u), "l"(C.u));
    return D.f;
}
__device__ __forceinline__ float2 fadd2(float2 a, float2 b) {
    union F2U { float2 f; unsigned long long u; };
    F2U A, Bv, D;
    A.f = a; Bv.f = b;
    asm("add.rn.f32x2 %0, %1, %2;" : "=l"(D.u) : "l"(A.u), "l"(Bv.u));
    return D.f;
}

// ---------------------------------------------------------------------------
// Prep 1: split emb (f32) into bf16 hi + lo planes. 4 elems / thread.
// ---------------------------------------------------------------------------
__global__ void __launch_bounds__(256)
emb_split_kernel(const float* __restrict__ emb)
{
    const int idx = (blockIdx.x * 256 + threadIdx.x) * 4;
    float4 v = *(const float4*)&emb[idx];
    __nv_bfloat16 h0 = __float2bfloat16(v.x), h1 = __float2bfloat16(v.y);
    __nv_bfloat16 h2 = __float2bfloat16(v.z), h3 = __float2bfloat16(v.w);
    __nv_bfloat16 l0 = __float2bfloat16(v.x - __bfloat162float(h0));
    __nv_bfloat16 l1 = __float2bfloat16(v.y - __bfloat162float(h1));
    __nv_bfloat16 l2 = __float2bfloat16(v.z - __bfloat162float(h2));
    __nv_bfloat16 l3 = __float2bfloat16(v.w - __bfloat162float(h3));
    *(__nv_bfloat162*)&g_ehi[idx]     = __nv_bfloat162(h0, h1);
    *(__nv_bfloat162*)&g_ehi[idx + 2] = __nv_bfloat162(h2, h3);
    *(__nv_bfloat162*)&g_elo[idx]     = __nv_bfloat162(l0, l1);
    *(__nv_bfloat162*)&g_elo[idx + 2] = __nv_bfloat162(l2, l3);
}

// ---------------------------------------------------------------------------
// Prep 2: W1 (1536 x 256) -> B[n][k] bf16 hi/lo, n = half*256 + d (512 rows).
// ---------------------------------------------------------------------------
__global__ void __launch_bounds__(256)
w_split_kernel(const float* __restrict__ W1)
{
    const int idx = blockIdx.x * 256 + threadIdx.x;     // 512 * 192
    const int k4 = idx % (H_ / 4);
    const int n  = idx / (H_ / 4);                       // 0..511
    const int half = n >> 8;
    const int d    = n & 255;
    const int k = k4 * 4;

    __nv_bfloat16 h[4], l[4];
    #pragma unroll
    for (int e = 0; e < 4; e++) {
        float x = W1[(half * H_ + k + e) * HID_ + d];
        h[e] = __float2bfloat16(x);
        l[e] = __float2bfloat16(x - __bfloat162float(h[e]));
    }
    const int o = n * H_ + k;
    *(__nv_bfloat162*)&g_bhi[o]     = __nv_bfloat162(h[0], h[1]);
    *(__nv_bfloat162*)&g_bhi[o + 2] = __nv_bfloat162(h[2], h[3]);
    *(__nv_bfloat162*)&g_blo[o]     = __nv_bfloat162(l[0], l[1]);
    *(__nv_bfloat162*)&g_blo[o + 2] = __nv_bfloat162(l[2], l[3]);
}

// ---------------------------------------------------------------------------
// GEMM: D[2048, 512] = sum over 3 planes of A_p (2048x768) @ B_p^T (512x768)
// CTA 128m x 64n, 256 thr (8 warps: warp_m = wid&3, warp_n = wid>>2, 32x32).
// BK=64 -> 36 iters (12 k-chunks x 3 planes). cp.async double-buffer,
// SW128 swizzle on 128B rows (no padding, 48KB static smem exactly).
// Epilogue: d-major store to g_a/g_c, +b1 on half 0. Grid 8 x 16 = 128 CTAs.
// ---------------------------------------------------------------------------
#define GITER 36
#define A_BUF_BYTES (128 * 128)   // 16KB per buffer
#define B_BUF_BYTES (64 * 128)    //  8KB per buffer

__global__ void __launch_bounds__(256)
gemm_kernel(const float* __restrict__ b1)
{
    __shared__ __align__(1024) unsigned char sraw[2 * A_BUF_BYTES + 2 * B_BUF_BYTES];

    const int t      = threadIdx.x;
    const int lane   = t & 31;
    const int wid    = t >> 5;
    const int warp_m = wid & 3;           // 32 m each
    const int warp_n = wid >> 2;          // 32 n each
    const int m0     = blockIdx.y * 128;
    const int ng0    = blockIdx.x * 64;   // global n (0..511)
    const int half   = ng0 >> 8;
    const int d0     = ng0 & 255;

    const uint32_t smemA = smem_u32(sraw);                 // A0, A1
    const uint32_t smemB = smemA + 2 * A_BUF_BYTES;        // B0, B1

    // ---- async fill: A 4 slots/thread, B 2 slots/thread (16B slots) -------
    auto fill = [&](int buf, int it) {
        const __nv_bfloat16* __restrict__ ea = (it < 24) ? g_ehi : g_elo;
        const __nv_bfloat16* __restrict__ eb =
            (it >= 12 && it < 24) ? g_blo : g_bhi;
        const int k0 = (it % 12) * 64;
        const uint32_t ab = smemA + buf * A_BUF_BYTES;
        const uint32_t bb = smemB + buf * B_BUF_BYTES;
        #pragma unroll
        for (int e = 0; e < 4; e++) {
            const int slot = t + e * 256;
            const int row = slot >> 3, seg = slot & 7;
            const uint32_t off = (uint32_t)(row * 128 + seg * 16);
            cp_async16(ab + SW128(off), &ea[(m0 + row) * H_ + k0 + seg * 8]);
        }
        #pragma unroll
        for (int e = 0; e < 2; e++) {
            const int slot = t + e * 256;
            const int row = slot >> 3, seg = slot & 7;
            const uint32_t off = (uint32_t)(row * 128 + seg * 16);
            cp_async16(bb + SW128(off), &eb[(ng0 + row) * H_ + k0 + seg * 8]);
        }
    };

    // ---- ldmatrix addressing (per-lane, swizzle-aware) --------------------
    const uint32_t csel  = (uint32_t)((lane >> 4) * 16);   // k-half select
    const uint32_t maskx = (uint32_t)((lane & 7) * 16);    // swizzle XOR mask
    const uint32_t aoff0 = (uint32_t)((warp_m * 32 + (lane & 15)) * 128);
    const uint32_t aoff1 = aoff0 + 16 * 128;
    const uint32_t boff0 = (uint32_t)((warp_n * 32 + (lane & 15)) * 128);
    const uint32_t boff1 = boff0 + 16 * 128;

    float acc[2][4][4];
    #pragma unroll
    for (int mf = 0; mf < 2; mf++)
        #pragma unroll
        for (int nf = 0; nf < 4; nf++)
            #pragma unroll
            for (int e = 0; e < 4; e++) acc[mf][nf][e] = 0.f;

    fill(0, 0);
    cp_commit();
    cp_wait0();
    __syncthreads();

    for (int it = 0; it < GITER; it++) {
        const int cur = it & 1;
        if (it + 1 < GITER) { fill(1 - cur, it + 1); cp_commit(); }

        const uint32_t ab = smemA + cur * A_BUF_BYTES;
        const uint32_t bb = smemB + cur * B_BUF_BYTES;
        #pragma unroll
        for (int kk = 0; kk < 4; kk++) {
            const uint32_t col = ((uint32_t)(kk * 32) + csel) ^ maskx;
            uint32_t a0[4], a1[4], b0[4], b1r[4];
            ldmx4(ab + aoff0 + col, a0);
            ldmx4(ab + aoff1 + col, a1);
            ldmx4(bb + boff0 + col, b0);
            ldmx4(bb + boff1 + col, b1r);
            mma16816(acc[0][0], a0, b0[0],  b0[2]);
            mma16816(acc[0][1], a0, b0[1],  b0[3]);
            mma16816(acc[0][2], a0, b1r[0], b1r[2]);
            mma16816(acc[0][3], a0, b1r[1], b1r[3]);
            mma16816(acc[1][0], a1, b0[0],  b0[2]);
            mma16816(acc[1][1], a1, b0[1],  b0[3]);
            mma16816(acc[1][2], a1, b1r[0], b1r[2]);
            mma16816(acc[1][3], a1, b1r[1], b1r[3]);
        }

        if (it + 1 < GITER) {
            cp_wait0();
            __syncthreads();
        }
    }

    // ---- epilogue: d-major store (+b1 on half 0) --------------------------
    float* __restrict__ gout = half ? g_c : g_a;
    const int mrow = m0 + warp_m * 32 + (lane >> 2);
    #pragma unroll
    for (int mf = 0; mf < 2; mf++) {
        const int m = mrow + mf * 16;
        #pragma unroll
        for (int nf = 0; nf < 4; nf++) {
            const int nl = warp_n * 32 + nf * 8 + (lane & 3) * 2;
            float bias0 = 0.f, bias1 = 0.f;
            if (half == 0) { bias0 = b1[d0 + nl]; bias1 = b1[d0 + nl + 1]; }
            const int d = d0 + nl;
            gout[d       * M_ + m]     = acc[mf][nf][0] + bias0;
            gout[(d + 1) * M_ + m]     = acc[mf][nf][1] + bias1;
            gout[d       * M_ + m + 8] = acc[mf][nf][2] + bias0;
            gout[(d + 1) * M_ + m + 8] = acc[mf][nf][3] + bias1;
        }
    }
}

// ---------------------------------------------------------------------------
// Pair kernel: unchanged (32x32 tiles, 64 thr, 4x4/thread, d-major scratch,
// double-buffered smem + reg prefetch). Measured 34.4us.
// ---------------------------------------------------------------------------
#define PDK  32
#define PDIT (HID_ / PDK)   // 8

__global__ void __launch_bounds__(64)
pair_kernel(const float* __restrict__ W2, const float* __restrict__ b2,
            float* __restrict__ out)
{
    const int b  = blockIdx.z;
    const int i0 = blockIdx.y * 32;
    const int j0 = blockIdx.x * 32;
    const int ma = b * N_ + i0;
    const int mc = b * N_ + j0;

    __shared__ float As[2][PDK][36];
    __shared__ float Cs[2][PDK][36];
    __shared__ float Ws[HID_];

    const int t  = threadIdx.x;
    const int tx = t & 7;
    const int ty = t >> 3;

    Ws[t] = W2[t]; Ws[t + 64] = W2[t + 64];
    Ws[t + 128] = W2[t + 128]; Ws[t + 192] = W2[t + 192];

    const int fdk = t >> 1;
    const int fs  = (t & 1) * 16;

    float4 paf[4], pcf[4];
    {
        const float* __restrict__ pa = &g_a[fdk * M_ + ma + fs];
        const float* __restrict__ pc = &g_c[fdk * M_ + mc + fs];
        #pragma unroll
        for (int e = 0; e < 4; e++) { paf[e] = *(const float4*)(pa + 4*e);
                                      pcf[e] = *(const float4*)(pc + 4*e); }
        #pragma unroll
        for (int e = 0; e < 4; e++) {
            *(float4*)&As[0][fdk][fs + 4*e] = paf[e];
            *(float4*)&Cs[0][fdk][fs + 4*e] = pcf[e];
        }
    }
    __syncthreads();

    float2 acc[4][2];
    #pragma unroll
    for (int mi = 0; mi < 4; mi++) {
        acc[mi][0] = make_float2(0.f, 0.f);
        acc[mi][1] = make_float2(0.f, 0.f);
    }

    for (int it = 0; it < PDIT; it++) {
        const int cur = it & 1;
        if (it + 1 < PDIT) {
            const int dd = (it + 1) * PDK;
            const float* __restrict__ pa = &g_a[(dd + fdk) * M_ + ma + fs];
            const float* __restrict__ pc = &g_c[(dd + fdk) * M_ + mc + fs];
            #pragma unroll
            for (int e = 0; e < 4; e++) { paf[e] = *(const float4*)(pa + 4*e);
                                          pcf[e] = *(const float4*)(pc + 4*e); }
        }

        const int dbase = it * PDK;
        #pragma unroll
        for (int g = 0; g < PDK / 4; g++) {
            const float4 wv = *(const float4*)&Ws[dbase + g * 4];
            const float wr[4] = {wv.x, wv.y, wv.z, wv.w};
            #pragma unroll
            for (int e = 0; e < 4; e++) {
                const int dk = g * 4 + e;
                const float2 wp = make_float2(wr[e], wr[e]);
                const float4 av = *(const float4*)&As[cur][dk][ty * 4];
                const float4 cv = *(const float4*)&Cs[cur][dk][tx * 4];
                const float2 c01 = make_float2(cv.x, cv.y);
                const float2 c23 = make_float2(cv.z, cv.w);
                const float am[4] = {av.x, av.y, av.z, av.w};
                #pragma unroll
                for (int mi = 0; mi < 4; mi++) {
                    const float2 ap = make_float2(am[mi], am[mi]);
                    float2 s0 = fadd2(ap, c01);
                    float2 s1 = fadd2(ap, c23);
                    s0.x = fmaxf(s0.x, 0.f); s0.y = fmaxf(s0.y, 0.f);
                    s1.x = fmaxf(s1.x, 0.f); s1.y = fmaxf(s1.y, 0.f);
                    acc[mi][0] = ffma2(s0, wp, acc[mi][0]);
                    acc[mi][1] = ffma2(s1, wp, acc[mi][1]);
                }
            }
        }

        if (it + 1 < PDIT) {
            const int nb = 1 - cur;
            #pragma unroll
            for (int e = 0; e < 4; e++) {
                *(float4*)&As[nb][fdk][fs + 4*e] = paf[e];
                *(float4*)&Cs[nb][fdk][fs + 4*e] = pcf[e];
            }
            __syncthreads();
        }
    }

    const float bb = b2[0];
    const int j = j0 + tx * 4;
    #pragma unroll
    for (int mi = 0; mi < 4; mi++) {
        const int i = i0 + ty * 4 + mi;
        float4 o;
        o.x = acc[mi][0].x + bb;
        o.y = acc[mi][0].y + bb;
        o.z = acc[mi][1].x + bb;
        o.w = acc[mi][1].y + bb;
        *(float4*)&out[((size_t)b * N_ + i) * N_ + j] = o;
    }
}

// ---------------------------------------------------------------------------
extern "C" void kernel_launch(void* const* d_in, const int* in_sizes, int n_in,
                              void* d_out, int out_size)
{
    const float* emb = (const float*)d_in[0];
    const float* W1  = (const float*)d_in[1];
    const float* b1  = (const float*)d_in[2];
    const float* W2  = (const float*)d_in[3];
    const float* b2  = (const float*)d_in[4];
    float* out = (float*)d_out;

    emb_split_kernel<<<(M_ * H_) / (256 * 4), 256>>>(emb);   // 1536 blocks
    w_split_kernel<<<(N_ * (H_ / 4)) / 256, 256>>>(W1);      // 384 blocks

    dim3 ggrid(N_ / 64, M_ / 128);                           // 8 x 16 = 128
    gemm_kernel<<<ggrid, 256>>>(b1);

    dim3 pgrid(N_ / 32, N_ / 32, B_);                        // 16 x 16 x 4
    pair_kernel<<<pgrid, 64>>>(W2, b2, out);
}